// round 10
// baseline (speedup 1.0000x reference)
#include <cuda_runtime.h>
#include <cuda_bf16.h>
#include <cstddef>

// score(f) = 1 + tanh(f.W + b)/10 ; e[parent] = score(c0)*e[c0] + score(c1)*e[c1]
// Complete binary tree, level order, D=21, N = 2^21 - 1, F = 64.
// Persistent kernel. Big levels: cp.async double-buffered 256-row block tiles,
// full-row dot from smem (1 shuffle/tile). Mid levels: warp tiles. Tail: block 0.

#define TANH_INV_SCALAR 0.1f
#define NB        148               // 1 block/SM -> all resident
#define NT        256
#define TILE      256               // children per block stage
#define RSTRIDE   68                // padded floats per row (LDS.128 conflict-floor)
#define STAGE_FLOATS (TILE * RSTRIDE)      // 17408
#define W_OFF     (2 * STAGE_FLOATS)
#define SMEM_BYTES ((W_OFF + 64) * 4)      // 139,520 B
#define NWARPS_G  (NB * (NT / 32))

__device__ unsigned g_count = 0;
__device__ volatile unsigned g_gen = 0;

__device__ __forceinline__ void grid_barrier()
{
    __syncthreads();
    if (threadIdx.x == 0) {
        __threadfence();
        unsigned g = g_gen;
        if (atomicAdd(&g_count, 1u) == NB - 1u) {
            g_count = 0;
            __threadfence();
            g_gen = g + 1u;
        } else {
            while (g_gen == g) { __nanosleep(32); }
            __threadfence();
        }
    }
    __syncthreads();
}

__device__ __forceinline__ float tanh_fast(float x)
{
    float y;
    asm("tanh.approx.f32 %0, %1;" : "=f"(y) : "f"(x));
    return y;
}

__device__ __forceinline__ void cp16(unsigned dst, const void* src)
{
    asm volatile("cp.async.cg.shared.global [%0], [%1], 16;"
                 :: "r"(dst), "l"(src));
}
#define CP_COMMIT() asm volatile("cp.async.commit_group;" ::: "memory")
template <int N> __device__ __forceinline__ void cp_wait()
{ asm volatile("cp.async.wait_group %0;" :: "n"(N) : "memory"); }

// Issue the 16 cp.asyncs for one 256-row tile into stage s (if tile valid).
__device__ __forceinline__ void stage_load(float* sm, int s,
                                           const float* __restrict__ features,
                                           int cstart, int tile, int ntiles, int tid)
{
    if (tile < ntiles) {
        unsigned base = (unsigned)__cvta_generic_to_shared(sm + s * STAGE_FLOATS);
        const float* g = features + (size_t)(cstart + tile * TILE) * 64;
        const int rb = tid >> 4, c = tid & 15;
        #pragma unroll
        for (int j = 0; j < 16; ++j) {
            int r = j * 16 + rb;
            unsigned dst = base + (unsigned)(r * RSTRIDE + c * 4) * 4u;
            cp16(dst, g + (size_t)(j * 256 + tid) * 4);
        }
    }
    CP_COMMIT();     // always commit (possibly empty group) to keep counts aligned
}

// R7-style 16-child warp tile (used for mid/tail levels).
__device__ __forceinline__ void do_tile(
    const float* __restrict__ features, float* __restrict__ energy,
    float4 wv, float b, int cstart, int pstart, int tile,
    int lane, int r, int vi)
{
    const int cbase = cstart + tile * 16;
    const bool s3 = lane & 8, s2 = lane & 4, s1 = lane & 2;
    const int h = lane >> 4;
    const int ci = cbase + r;
    float e = __ldcg(&energy[ci]);
    const float4* g = reinterpret_cast<const float4*>(features + (size_t)cbase * 64);
    float part[8];
    #pragma unroll
    for (int j = 0; j < 8; ++j) {
        float4 v = __ldg(&g[j * 32 + lane]);
        part[j] = v.x * wv.x + v.y * wv.y + v.z * wv.z + v.w * wv.w;
    }
    float a4[4];
    #pragma unroll
    for (int j = 0; j < 4; ++j) {
        float u0 = part[2*j]   + __shfl_xor_sync(~0u, part[2*j],   8);
        float u1 = part[2*j+1] + __shfl_xor_sync(~0u, part[2*j+1], 8);
        a4[j] = s3 ? u1 : u0;
    }
    float a2[2];
    #pragma unroll
    for (int j = 0; j < 2; ++j) {
        float u0 = a4[2*j]   + __shfl_xor_sync(~0u, a4[2*j],   4);
        float u1 = a4[2*j+1] + __shfl_xor_sync(~0u, a4[2*j+1], 4);
        a2[j] = s2 ? u1 : u0;
    }
    float u0 = a2[0] + __shfl_xor_sync(~0u, a2[0], 2);
    float u1 = a2[1] + __shfl_xor_sync(~0u, a2[1], 2);
    float a1 = s1 ? u1 : u0;
    float dot = a1 + __shfl_xor_sync(~0u, a1, 1);
    float s = 1.0f + tanh_fast(dot + b) * TANH_INV_SCALAR;
    float contrib = s * e;
    float other = __shfl_xor_sync(~0u, contrib, 16);
    if (h == 0 && (lane & 1) == 0)
        __stcg(&energy[pstart + tile * 8 + vi], contrib + other);
}

__global__ void __launch_bounds__(NT)
tree_all_kernel(const float* __restrict__ features,
                const float* __restrict__ leaf_energy,
                const float* __restrict__ W,
                const float* __restrict__ bptr,
                float* __restrict__ energy)
{
    extern __shared__ float sm[];
    const int tid  = threadIdx.x;
    const int lane = tid & 31;
    const int gwarp = (blockIdx.x * NT + tid) >> 5;

    if (tid < 64) sm[W_OFF + tid] = W[tid];
    const float b = __ldg(bptr);
    const float4 wv = reinterpret_cast<const float4*>(W)[lane & 15];
    const int h  = lane >> 4;
    const int vi = ((lane >> 3) & 1) | (((lane >> 2) & 1) << 1)
                 | (((lane >> 1) & 1) << 2);
    const int rr = 2 * vi + h;
    __syncthreads();

    const int NLEAF = 1 << 20;
    const int leaf_start = NLEAF - 1;

    // ---- Staged levels d = 20 .. 12 (256-row block tiles, double buffered) ----
    for (int d = 20; d >= 12; --d) {
        const int nc     = 1 << d;
        const int cstart = nc - 1;
        const int pstart = (nc >> 1) - 1;
        const int ntiles = nc >> 8;
        const bool leaf_level = (d == 20);

        stage_load(sm, 0, features, cstart, blockIdx.x,            ntiles, tid);
        stage_load(sm, 1, features, cstart, blockIdx.x + NB,       ntiles, tid);

        int s = 0;
        for (int tile = blockIdx.x; tile < ntiles; tile += NB) {
            cp_wait<1>();
            __syncthreads();

            const int ci = cstart + tile * TILE + tid;
            float e;
            if (leaf_level) e = __ldg(&leaf_energy[ci - leaf_start]);
            else            e = __ldcg(&energy[ci]);

            const float* row = sm + s * STAGE_FLOATS + tid * RSTRIDE;
            float dot = 0.0f;
            #pragma unroll
            for (int k = 0; k < 16; ++k) {
                float4 f = *reinterpret_cast<const float4*>(row + k * 4);
                float4 w = *reinterpret_cast<const float4*>(sm + W_OFF + k * 4);
                dot += f.x * w.x + f.y * w.y + f.z * w.z + f.w * w.w;
            }
            if (leaf_level) __stcg(&energy[ci], e);   // seed output leaves

            float sc = 1.0f + tanh_fast(dot + b) * TANH_INV_SCALAR;
            float contrib = sc * e;
            float other = __shfl_xor_sync(~0u, contrib, 1);
            if ((tid & 1) == 0)
                __stcg(&energy[pstart + tile * (TILE / 2) + (tid >> 1)],
                       contrib + other);

            __syncthreads();                        // stage s fully consumed
            stage_load(sm, s, features, cstart, tile + 2 * NB, ntiles, tid);
            s ^= 1;
        }
        cp_wait<0>();
        grid_barrier();
    }

    // ---- Mid levels d = 11, 10 : grid-wide 16-child warp tiles ----
    for (int d = 11; d >= 10; --d) {
        const int nc     = 1 << d;
        const int cstart = nc - 1;
        const int pstart = (nc >> 1) - 1;
        const int ntiles = nc >> 4;
        for (int tile = gwarp; tile < ntiles; tile += NWARPS_G)
            do_tile(features, energy, wv, b, cstart, pstart, tile, lane, rr, vi);
        grid_barrier();
    }

    // ---- Tail: block 0 only ----
    if (blockIdx.x != 0) return;
    const int bwarp = tid >> 5;

    for (int d = 9; d >= 5; --d) {
        const int nc     = 1 << d;
        const int cstart = nc - 1;
        const int pstart = (nc >> 1) - 1;
        const int ntiles = nc >> 4;
        for (int tile = bwarp; tile < ntiles; tile += NT / 32)
            do_tile(features, energy, wv, b, cstart, pstart, tile, lane, rr, vi);
        __syncthreads();
    }

    for (int d = 4; d >= 1; --d) {
        const int nc     = 1 << d;
        const int cstart = nc - 1;
        const int pstart = (nc >> 1) - 1;
        if (tid < 32) {
            float contrib = 0.0f;
            if (lane < nc) {
                const int ch = cstart + lane;
                const float* f = features + (size_t)ch * 64;
                float dot = 0.0f;
                #pragma unroll
                for (int k = 0; k < 64; ++k)
                    dot += __ldg(&f[k]) * sm[W_OFF + k];
                float s = 1.0f + tanh_fast(dot + b) * TANH_INV_SCALAR;
                contrib = s * __ldcg(&energy[ch]);
            }
            float other = __shfl_xor_sync(~0u, contrib, 1);
            if (lane < nc && (lane & 1) == 0)
                __stcg(&energy[pstart + (lane >> 1)], contrib + other);
        }
        __syncthreads();
    }
}

extern "C" void kernel_launch(void* const* d_in, const int* in_sizes, int n_in,
                              void* d_out, int out_size)
{
    const float* features    = (const float*)d_in[0];   // [N, 64]
    const float* leaf_energy = (const float*)d_in[1];   // [2^20]
    const float* W           = (const float*)d_in[2];   // [64]
    const float* bptr        = (const float*)d_in[3];   // [1]
    float* energy = (float*)d_out;                      // [N]

    cudaFuncSetAttribute(tree_all_kernel,
                         cudaFuncAttributeMaxDynamicSharedMemorySize, SMEM_BYTES);
    tree_all_kernel<<<NB, NT, SMEM_BYTES>>>(features, leaf_energy, W, bptr, energy);
}

// round 11
// speedup vs baseline: 1.4548x; 1.4548x over previous
#include <cuda_runtime.h>
#include <cuda_bf16.h>
#include <cstddef>

// score(f) = 1 + tanh(f.W + b)/10 ; e[parent] = score(c0)*e[c0] + score(c1)*e[c1]
// Complete binary tree, level order, D=21, N = 2^21 - 1, F = 64.
// Phase A: flat pass over ALL rows (no barriers): internal rows -> g_scores,
//          leaf rows -> contrib + level-19 parents directly.
// Phase B: levels 19..12 as tiny score-lookup passes (grid barriers),
//          levels 11..1 on block 0. Lean 1-buffer pipeline in phase A.

#define TANH_INV_SCALAR 0.1f
#define NB       444        // 3 blocks/SM on 148 SMs -> all resident
#define NT       256
#define NWARPS   (NB * (NT / 32))
#define NTH      (NB * NT)

#define LEAF_START ((1 << 20) - 1)
#define N_INT_TILES (1 << 16)     // tiles covering rows 0 .. 2^20-1
#define N_TILES     (1 << 17)     // + 65536 leaf tiles

__device__ float g_scores[1 << 20];     // scores for internal nodes (by node id)
__device__ unsigned g_count = 0;
__device__ volatile unsigned g_gen = 0;

__device__ __forceinline__ void grid_barrier()
{
    __syncthreads();
    if (threadIdx.x == 0) {
        __threadfence();
        unsigned g = g_gen;
        if (atomicAdd(&g_count, 1u) == NB - 1u) {
            g_count = 0;
            __threadfence();
            g_gen = g + 1u;
        } else {
            while (g_gen == g) { __nanosleep(32); }
            __threadfence();
        }
    }
    __syncthreads();
}

__device__ __forceinline__ float tanh_fast(float x)
{
    float y;
    asm("tanh.approx.f32 %0, %1;" : "=f"(y) : "f"(x));
    return y;
}

__device__ __forceinline__ int tile_base(int T)
{
    return (T < N_INT_TILES) ? (T << 4)
                             : LEAF_START + ((T - N_INT_TILES) << 4);
}

__device__ __forceinline__ void issue_loads(const float* __restrict__ features,
                                            int cb, int lane, float4 v[8])
{
    const float4* g = reinterpret_cast<const float4*>(features + (size_t)cb * 64);
    #pragma unroll
    for (int j = 0; j < 8; ++j)
        v[j] = __ldg(&g[j * 32 + lane]);
}

__global__ void __launch_bounds__(NT, 3)
tree_all_kernel(const float* __restrict__ features,
                const float* __restrict__ leaf_energy,
                const float* __restrict__ W,
                const float* __restrict__ bptr,
                float* __restrict__ energy)
{
    const int tid   = threadIdx.x;
    const int lane  = tid & 31;
    const int gtid  = blockIdx.x * NT + tid;
    const int gwarp = gtid >> 5;

    const float4 wv = reinterpret_cast<const float4*>(W)[lane & 15];
    const float  b  = __ldg(bptr);

    const bool s3 = lane & 8, s2 = lane & 4, s1 = lane & 2;
    const int  h  = lane >> 4;
    const int  vi = ((lane >> 3) & 1) | (((lane >> 2) & 1) << 1)
                  | (((lane >> 1) & 1) << 2);
    const int  rr = 2 * vi + h;

    // ================= Phase A: flat scoring pass, 1-buffer pipeline ========
    {
        int T = gwarp;
        float4 v[8];
        if (T < N_TILES)
            issue_loads(features, tile_base(T), lane, v);

        while (T < N_TILES) {
            const int  cb      = tile_base(T);
            const bool is_leaf = (T >= N_INT_TILES);
            const int  Tn      = T + NWARPS;

            // Consume current buffer into 8 scalars (waits on T's loads).
            float part[8];
            #pragma unroll
            for (int j = 0; j < 8; ++j)
                part[j] = v[j].x * wv.x + v[j].y * wv.y
                        + v[j].z * wv.z + v[j].w * wv.w;

            // Leaf-energy prefetch for this tile (independent of butterfly).
            float e = 0.0f;
            if (is_leaf)
                e = __ldg(&leaf_energy[cb + rr - LEAF_START]);

            // Issue NEXT tile's loads now -> in flight through the butterfly.
            if (Tn < N_TILES)
                issue_loads(features, tile_base(Tn), lane, v);

            // Folding butterfly: every lane ends with full dot of row rr.
            float a4[4];
            #pragma unroll
            for (int j = 0; j < 4; ++j) {
                float u0 = part[2*j]   + __shfl_xor_sync(~0u, part[2*j],   8);
                float u1 = part[2*j+1] + __shfl_xor_sync(~0u, part[2*j+1], 8);
                a4[j] = s3 ? u1 : u0;
            }
            float a2[2];
            #pragma unroll
            for (int j = 0; j < 2; ++j) {
                float u0 = a4[2*j]   + __shfl_xor_sync(~0u, a4[2*j],   4);
                float u1 = a4[2*j+1] + __shfl_xor_sync(~0u, a4[2*j+1], 4);
                a2[j] = s2 ? u1 : u0;
            }
            float u0 = a2[0] + __shfl_xor_sync(~0u, a2[0], 2);
            float u1 = a2[1] + __shfl_xor_sync(~0u, a2[1], 2);
            float a1 = s1 ? u1 : u0;
            float dot = a1 + __shfl_xor_sync(~0u, a1, 1);

            float sc = 1.0f + tanh_fast(dot + b) * TANH_INV_SCALAR;

            if (!is_leaf) {
                if ((lane & 1) == 0 && cb + rr < LEAF_START)
                    __stcg(&g_scores[cb + rr], sc);
            } else {
                if ((lane & 1) == 0)
                    __stcg(&energy[cb + rr], e);          // seed output leaves
                float contrib = sc * e;
                float other = __shfl_xor_sync(~0u, contrib, 16);
                if (h == 0 && (lane & 1) == 0) {
                    const int t = T - N_INT_TILES;
                    __stcg(&energy[(1 << 19) - 1 + 8 * t + vi],
                           contrib + other);              // level-19 parents
                }
            }
            T = Tn;
        }
    }
    grid_barrier();

    // ================= Phase B: levels d = 19 .. 12 (score lookups) =========
    for (int d = 19; d >= 12; --d) {
        const int np     = 1 << (d - 1);
        const int pstart = np - 1;
        for (int i = gtid; i < np; i += NTH) {
            const int p = pstart + i;
            const int c = 2 * p + 1;
            float s0 = __ldcg(&g_scores[c]);
            float s1 = __ldcg(&g_scores[c + 1]);
            float e0 = __ldcg(&energy[c]);
            float e1 = __ldcg(&energy[c + 1]);
            __stcg(&energy[p], s0 * e0 + s1 * e1);
        }
        grid_barrier();
    }

    // ================= Tail: levels d = 11 .. 1 on block 0 ==================
    if (blockIdx.x != 0) return;
    for (int d = 11; d >= 1; --d) {
        const int np     = 1 << (d - 1);
        const int pstart = np - 1;
        for (int i = tid; i < np; i += NT) {
            const int p = pstart + i;
            const int c = 2 * p + 1;
            float s0 = __ldcg(&g_scores[c]);
            float s1 = __ldcg(&g_scores[c + 1]);
            float e0 = __ldcg(&energy[c]);
            float e1 = __ldcg(&energy[c + 1]);
            __stcg(&energy[p], s0 * e0 + s1 * e1);
        }
        __syncthreads();
    }
}

extern "C" void kernel_launch(void* const* d_in, const int* in_sizes, int n_in,
                              void* d_out, int out_size)
{
    const float* features    = (const float*)d_in[0];   // [N, 64]
    const float* leaf_energy = (const float*)d_in[1];   // [2^20]
    const float* W           = (const float*)d_in[2];   // [64]
    const float* bptr        = (const float*)d_in[3];   // [1]
    float* energy = (float*)d_out;                      // [N]

    tree_all_kernel<<<NB, NT>>>(features, leaf_energy, W, bptr, energy);
}